// round 6
// baseline (speedup 1.0000x reference)
#include <cuda_runtime.h>
#include <cstdint>

#define NIMG 4
#define PBINS 10
#define LBINS 6
#define IBINS 60              // inter bins (l*10+p) in smem
#define NBINS 66              // + 6 label-count bins (60+l) in registers
#define TPB 128
#define NWARPS (TPB/32)
#define BLOCKS_PER_IMG 64
#define TOTAL_BLOCKS (BLOCKS_PER_IMG * NIMG)          // 256
#define VECS_PER_IMG (1024*1024/4)                    // 262144
#define VECS_PER_BLOCK (VECS_PER_IMG/BLOCKS_PER_IMG)  // 4096
#define TILE_VECS 512
#define NTILES (VECS_PER_BLOCK/TILE_VECS)             // 8
#define VECS_PER_THREAD (TILE_VECS/TPB)               // 4
#define TILE_BYTES (TILE_VECS*16)                     // 8192

// Dynamic smem layout (bytes)
#define HIST_BYTES (IBINS*TPB*4)                      // 30720
#define TP_OFF(s) (HIST_BYTES + (s)*TILE_BYTES)
#define TC_OFF(s) (HIST_BYTES + 2*TILE_BYTES + (s)*TILE_BYTES)
#define TL_OFF(s) (HIST_BYTES + 4*TILE_BYTES + (s)*TILE_BYTES)
#define MBAR_OFF  (HIST_BYTES + 6*TILE_BYTES)         // 79872
#define FULL_OFF(s)  (MBAR_OFF + (s)*8)
#define EMPTY_OFF(s) (MBAR_OFF + 16 + (s)*8)
#define SMEM_TOTAL (MBAR_OFF + 32)                    // 79904

__device__ float g_bins[NIMG][NBINS];
__device__ unsigned int g_ticket;

__device__ __forceinline__ uint32_t smem_u32(const void* p) {
    uint32_t a;
    asm("{ .reg .u64 t; cvta.to.shared.u64 t, %1; cvt.u32.u64 %0, t; }"
        : "=r"(a) : "l"(p));
    return a;
}
__device__ __forceinline__ void mbar_init(uint32_t a, uint32_t cnt) {
    asm volatile("mbarrier.init.shared.b64 [%0], %1;" :: "r"(a), "r"(cnt) : "memory");
}
__device__ __forceinline__ void mbar_expect_tx(uint32_t a, uint32_t bytes) {
    asm volatile("mbarrier.arrive.expect_tx.shared.b64 _, [%0], %1;"
                 :: "r"(a), "r"(bytes) : "memory");
}
__device__ __forceinline__ void mbar_arrive(uint32_t a) {
    asm volatile("mbarrier.arrive.shared.b64 _, [%0];" :: "r"(a) : "memory");
}
__device__ __forceinline__ void mbar_wait(uint32_t a, uint32_t parity) {
    asm volatile(
        "{\n\t.reg .pred P;\n\t"
        "WL_%=:\n\t"
        "mbarrier.try_wait.parity.acquire.cta.shared::cta.b64 P, [%0], %1, 0x989680;\n\t"
        "@P bra.uni WD_%=;\n\t"
        "bra.uni WL_%=;\n\t"
        "WD_%=:\n\t}"
        :: "r"(a), "r"(parity) : "memory");
}
__device__ __forceinline__ void bulk_g2s(uint32_t dst, const void* src,
                                         uint32_t bytes, uint32_t mbar) {
    asm volatile(
        "cp.async.bulk.shared::cta.global.mbarrier::complete_tx::bytes [%0], [%1], %2, [%3];"
        :: "r"(dst), "l"(src), "r"(bytes), "r"(mbar) : "memory");
}

__global__ void __launch_bounds__(TPB)
sc_fused_kernel(const float* __restrict__ pred,
                const int* __restrict__ pconn,
                const int* __restrict__ lconn,
                float* __restrict__ out) {
    extern __shared__ char dyn[];
    float* hist = (float*)dyn;                 // [IBINS][TPB], private columns
    __shared__ float s_part[NBINS][NWARPS];
    __shared__ float losses[NIMG];
    __shared__ float binc[NIMG][NBINS];
    __shared__ bool  s_last;

    const int tid = threadIdx.x;
    const int img = blockIdx.y;
    const uint32_t sbase = smem_u32(dyn);

    #pragma unroll
    for (int b = 0; b < IBINS; b++) hist[b * TPB + tid] = 0.0f;
    if (tid == 0) {
        mbar_init(sbase + FULL_OFF(0), 1);
        mbar_init(sbase + FULL_OFF(1), 1);
        mbar_init(sbase + EMPTY_OFF(0), TPB);
        mbar_init(sbase + EMPTY_OFF(1), TPB);
    }
    __syncthreads();

    // Base vec index for this block.
    const size_t bvec = (size_t)img * VECS_PER_IMG + (size_t)blockIdx.x * VECS_PER_BLOCK;
    const char* __restrict__ pP = (const char*)pred  + bvec * 16;
    const char* __restrict__ pC = (const char*)pconn + bvec * 16;
    const char* __restrict__ pL = (const char*)lconn + bvec * 16;

    // Producer primes stages 0 and 1 (tiles 0,1). TMA engine streams at full
    // BW independent of warp stalls — this is the whole point of this round.
    if (tid == 0) {
        #pragma unroll
        for (int t = 0; t < 2; t++) {
            mbar_expect_tx(sbase + FULL_OFF(t), 3 * TILE_BYTES);
            bulk_g2s(sbase + TP_OFF(t), pP + (size_t)t * TILE_BYTES, TILE_BYTES, sbase + FULL_OFF(t));
            bulk_g2s(sbase + TC_OFF(t), pC + (size_t)t * TILE_BYTES, TILE_BYTES, sbase + FULL_OFF(t));
            bulk_g2s(sbase + TL_OFF(t), pL + (size_t)t * TILE_BYTES, TILE_BYTES, sbase + FULL_OFF(t));
        }
    }

    // Label counts: 6 byte-fields in one 64-bit register (128 px/thread max).
    unsigned long long cnt = 0ULL;

    #pragma unroll
    for (int t = 0; t < NTILES; t++) {
        const int s = t & 1;
        const int r = t >> 1;
        mbar_wait(sbase + FULL_OFF(s), r & 1);

        #pragma unroll
        for (int k = 0; k < VECS_PER_THREAD; k++) {
            int j = tid + k * TPB;
            float4 p = *(const float4*)(dyn + TP_OFF(s) + j * 16);
            int4   c = *(const int4*)  (dyn + TC_OFF(s) + j * 16);
            int4   l = *(const int4*)  (dyn + TL_OFF(s) + j * 16);
            hist[(l.x * PBINS + c.x) * TPB + tid] += p.x;
            hist[(l.y * PBINS + c.y) * TPB + tid] += p.y;
            hist[(l.z * PBINS + c.z) * TPB + tid] += p.z;
            hist[(l.w * PBINS + c.w) * TPB + tid] += p.w;
            cnt += (1ULL << (8 * l.x)) + (1ULL << (8 * l.y))
                 + (1ULL << (8 * l.z)) + (1ULL << (8 * l.w));
        }
        mbar_arrive(sbase + EMPTY_OFF(s));

        if (tid == 0 && t + 2 < NTILES) {
            // Refill this stage once all 128 consumers of round r are done.
            mbar_wait(sbase + EMPTY_OFF(s), r & 1);
            mbar_expect_tx(sbase + FULL_OFF(s), 3 * TILE_BYTES);
            bulk_g2s(sbase + TP_OFF(s), pP + (size_t)(t + 2) * TILE_BYTES, TILE_BYTES, sbase + FULL_OFF(s));
            bulk_g2s(sbase + TC_OFF(s), pC + (size_t)(t + 2) * TILE_BYTES, TILE_BYTES, sbase + FULL_OFF(s));
            bulk_g2s(sbase + TL_OFF(s), pL + (size_t)(t + 2) * TILE_BYTES, TILE_BYTES, sbase + FULL_OFF(s));
        }
    }
    __syncthreads();

    // Reduce 128 private columns per bin: warp shuffle, then 4 partials.
    const int lane = tid & 31;
    const int wid  = tid >> 5;
    #pragma unroll
    for (int b = 0; b < NBINS; b++) {
        float x;
        if (b < IBINS) x = hist[b * TPB + tid];   // bank = tid%32, conflict-free
        else           x = (float)((cnt >> (8 * (b - IBINS))) & 0xFFULL);
        x += __shfl_down_sync(0xFFFFFFFFu, x, 16);
        x += __shfl_down_sync(0xFFFFFFFFu, x, 8);
        x += __shfl_down_sync(0xFFFFFFFFu, x, 4);
        x += __shfl_down_sync(0xFFFFFFFFu, x, 2);
        x += __shfl_down_sync(0xFFFFFFFFu, x, 1);
        if (lane == 0) s_part[b][wid] = x;
    }
    __syncthreads();

    if (tid < NBINS) {
        float t = 0.0f;
        #pragma unroll
        for (int w = 0; w < NWARPS; w++) t += s_part[tid][w];
        atomicAdd(&g_bins[img][tid], t);
    }

    // ---- last-block-done: finalize inline, then restore scratch to zero ----
    if (tid == 0) {
        __threadfence();
        unsigned int tk = atomicAdd(&g_ticket, 1u);
        s_last = (tk == TOTAL_BLOCKS - 1);
    }
    __syncthreads();
    if (!s_last) return;

    #pragma unroll
    for (int c = 0; c < 3; c++) {
        int k = tid + c * TPB;
        if (k < NIMG * NBINS)
            ((float*)binc)[k] = __ldcg(&((const float*)g_bins)[k]);
    }
    __syncthreads();

    if (tid < NIMG) {
        const float* b = binc[tid];
        float pa[PBINS];
        #pragma unroll
        for (int p = 0; p < PBINS; p++) {
            float sum = 0.0f;
            #pragma unroll
            for (int l = 0; l < LBINS; l++) sum += b[l * PBINS + p];
            pa[p] = sum;
        }
        bool colnz[PBINS];
        #pragma unroll
        for (int p = 0; p < PBINS; p++) colnz[p] = false;

        float pair_conn_sum = 0.0f;
        #pragma unroll
        for (int l = 1; l < LBINS; l++) {
            float la = b[IBINS + l];
            float pc = 0.0f;
            int   pn = 0;
            #pragma unroll
            for (int p = 1; p < PBINS; p++) {
                float in = b[l * PBINS + p];
                if (in != 0.0f) {
                    float uni = la + pa[p] - in;
                    pc += in / uni;
                    pn++;
                    colnz[p] = true;
                }
            }
            if (pn > 0) pair_conn_sum += pc / (float)pn;
        }
        int lone = 0;
        #pragma unroll
        for (int p = 1; p < PBINS; p++) if (!colnz[p]) lone++;

        float denom = (float)(LBINS - 1) + (float)lone;
        losses[tid] = 1.0f - pair_conn_sum / denom;
    }
    __syncthreads();

    if (tid == 0)
        out[0] = (losses[0] + losses[1] + losses[2] + losses[3]) * 0.25f;

    #pragma unroll
    for (int c = 0; c < 3; c++) {
        int k = tid + c * TPB;
        if (k < NIMG * NBINS) ((float*)g_bins)[k] = 0.0f;
    }
    if (tid == 0) g_ticket = 0u;
}

extern "C" void kernel_launch(void* const* d_in, const int* in_sizes, int n_in,
                              void* d_out, int out_size) {
    const float* pred  = (const float*)d_in[0];
    const int*   pconn = (const int*)d_in[1];
    const int*   lconn = (const int*)d_in[2];
    float* out = (float*)d_out;

    cudaFuncSetAttribute(sc_fused_kernel,
                         cudaFuncAttributeMaxDynamicSharedMemorySize, SMEM_TOTAL);

    dim3 grid(BLOCKS_PER_IMG, NIMG);
    sc_fused_kernel<<<grid, TPB, SMEM_TOTAL>>>(pred, pconn, lconn, out);
}

// round 7
// speedup vs baseline: 1.1100x; 1.1100x over previous
#include <cuda_runtime.h>
#include <cstdint>

#define NIMG 4
#define PBINS 10
#define LBINS 6
#define NBINS 66                      // 60 inter bins + 6 label-count bins
#define TPB 256
#define NWARPS (TPB/32)               // 8
#define BLOCKS_PER_IMG 148            // one block per SM per image: 4 blocks/SM
#define TOTAL_BLOCKS (BLOCKS_PER_IMG * NIMG)   // 592 = 148*4, perfectly balanced
#define VECS_PER_IMG (1024*1024/4)    // 262144 float4 per image
#define STRIDE (BLOCKS_PER_IMG * TPB) // 37888
#define KITERS 7                      // 7*37888 = 265216 >= 262144 (guarded)

// Global scratch (zero-initialized at module load; kernel restores zeros
// before exit so every graph replay sees identical state).
__device__ float g_bins[NIMG][NBINS];
__device__ unsigned int g_ticket;

__global__ void __launch_bounds__(TPB, 4)
sc_fused_kernel(const float* __restrict__ pred,
                const int* __restrict__ pconn,
                const int* __restrict__ lconn,
                float* __restrict__ out) {
    // Per-WARP shared histograms (2 KB total) -> tiny smem, high occupancy.
    // whist[w][bin], 64-slot stride so each warp's hist spans all 32 banks.
    __shared__ float whist[NWARPS][64];
    __shared__ float scnt[LBINS];
    __shared__ float losses[NIMG];
    __shared__ float binc[NIMG][NBINS];
    __shared__ bool  s_last;

    const int tid  = threadIdx.x;
    const int lane = tid & 31;
    const int wid  = tid >> 5;
    const int img  = blockIdx.y;

    // Zero the 2 KB histograms + counts.
    #pragma unroll
    for (int k = tid; k < NWARPS * 64; k += TPB) ((float*)whist)[k] = 0.0f;
    if (tid < LBINS) scnt[tid] = 0.0f;
    __syncthreads();

    const size_t base = (size_t)img * VECS_PER_IMG;
    const float4* __restrict__ p4  = ((const float4*)pred)  + base;
    const int4*   __restrict__ pc4 = ((const int4*)pconn)   + base;
    const int4*   __restrict__ lc4 = ((const int4*)lconn)   + base;

    float* const myhist = whist[wid];

    // Label counts: 6 byte-fields packed in a 64-bit register.
    // <= 28 pixels/thread per label -> fields never overflow 8 bits.
    unsigned long long cnt = 0ULL;

    int v = blockIdx.x * TPB + tid;
    #pragma unroll
    for (int k = 0; k < KITERS; k++, v += STRIDE) {
        if (v < VECS_PER_IMG) {
            float4 p = p4[v];
            int4   c = pc4[v];
            int4   l = lc4[v];
            atomicAdd(&myhist[l.x * PBINS + c.x], p.x);
            atomicAdd(&myhist[l.y * PBINS + c.y], p.y);
            atomicAdd(&myhist[l.z * PBINS + c.z], p.z);
            atomicAdd(&myhist[l.w * PBINS + c.w], p.w);
            cnt += (1ULL << (8 * l.x)) + (1ULL << (8 * l.y))
                 + (1ULL << (8 * l.z)) + (1ULL << (8 * l.w));
        }
    }

    // Warp-reduce packed counts. Split 8-bit fields into two words of
    // 16-bit-spaced fields so sums over 32 lanes (<=896) don't overflow.
    unsigned long long lo = cnt & 0x00FF00FF00FF00FFULL;         // labels 0,2,4
    unsigned long long hi = (cnt >> 8) & 0x00FF00FF00FF00FFULL;  // labels 1,3,5
    #pragma unroll
    for (int d = 16; d > 0; d >>= 1) {
        lo += __shfl_down_sync(0xFFFFFFFFu, lo, d);
        hi += __shfl_down_sync(0xFFFFFFFFu, hi, d);
    }
    if (lane == 0) {
        #pragma unroll
        for (int l = 0; l < 3; l++) {
            atomicAdd(&scnt[2 * l],     (float)((lo >> (16 * l)) & 0xFFFFULL));
            atomicAdd(&scnt[2 * l + 1], (float)((hi >> (16 * l)) & 0xFFFFULL));
        }
    }
    __syncthreads();

    // Fold 8 warp-histograms + counts into global bins.
    if (tid < 60) {
        float t = 0.0f;
        #pragma unroll
        for (int w = 0; w < NWARPS; w++) t += whist[w][tid];
        atomicAdd(&g_bins[img][tid], t);
    } else if (tid < NBINS) {
        atomicAdd(&g_bins[img][tid], scnt[tid - 60]);
    }

    // ---- last-block-done: finalize inline, then restore scratch to zero ----
    if (tid == 0) {
        __threadfence();
        unsigned int tk = atomicAdd(&g_ticket, 1u);
        s_last = (tk == TOTAL_BLOCKS - 1);
    }
    __syncthreads();
    if (!s_last) return;

    // All blocks' atomics visible (threadfence-before-ticket). Read via L2.
    if (tid < NIMG * NBINS)
        ((float*)binc)[tid] = __ldcg(&((const float*)g_bins)[tid]);
    {
        int k = tid + TPB;
        if (k < NIMG * NBINS)
            ((float*)binc)[k] = __ldcg(&((const float*)g_bins)[k]);
    }
    __syncthreads();

    if (tid < NIMG) {
        const float* b = binc[tid];

        // pred_area[p] = sum_l inter[l][p]
        float pa[PBINS];
        #pragma unroll
        for (int p = 0; p < PBINS; p++) {
            float sum = 0.0f;
            #pragma unroll
            for (int l = 0; l < LBINS; l++) sum += b[l * PBINS + p];
            pa[p] = sum;
        }

        bool colnz[PBINS];
        #pragma unroll
        for (int p = 0; p < PBINS; p++) colnz[p] = false;

        float pair_conn_sum = 0.0f;
        #pragma unroll
        for (int l = 1; l < LBINS; l++) {
            float la = b[60 + l];
            float pc = 0.0f;
            int   pn = 0;
            #pragma unroll
            for (int p = 1; p < PBINS; p++) {
                float in = b[l * PBINS + p];
                if (in != 0.0f) {
                    float uni = la + pa[p] - in;
                    pc += in / uni;
                    pn++;
                    colnz[p] = true;
                }
            }
            if (pn > 0) pair_conn_sum += pc / (float)pn;
        }

        int lone = 0;
        #pragma unroll
        for (int p = 1; p < PBINS; p++) if (!colnz[p]) lone++;

        float denom = (float)(LBINS - 1) + (float)lone;
        losses[tid] = 1.0f - pair_conn_sum / denom;
    }
    __syncthreads();

    if (tid == 0)
        out[0] = (losses[0] + losses[1] + losses[2] + losses[3]) * 0.25f;

    // Restore scratch to zero for the next (graph-replayed) call.
    if (tid < NIMG * NBINS) ((float*)g_bins)[tid] = 0.0f;
    {
        int k = tid + TPB;
        if (k < NIMG * NBINS) ((float*)g_bins)[k] = 0.0f;
    }
    if (tid == 0) g_ticket = 0u;
}

extern "C" void kernel_launch(void* const* d_in, const int* in_sizes, int n_in,
                              void* d_out, int out_size) {
    const float* pred  = (const float*)d_in[0];
    const int*   pconn = (const int*)d_in[1];
    const int*   lconn = (const int*)d_in[2];
    float* out = (float*)d_out;

    dim3 grid(BLOCKS_PER_IMG, NIMG);
    sc_fused_kernel<<<grid, TPB>>>(pred, pconn, lconn, out);
}